// round 15
// baseline (speedup 1.0000x reference)
#include <cuda_runtime.h>
#include <cuda_fp16.h>
#include <cstdint>

#define BB 16
#define TT 2048
#define DD 1024
#define HH 128
#define BT (BB*TT)

// Packed block: 128 rows x 64 halves = 8192 halves = 16384 B, SW-XOR baked in.
#define BLKH 8192
#define BLKB 16384

// ---------------- device scratch (allocation-free rule) ----------------
__device__ __align__(128) __half g_xp[(size_t)BT*DD];      // packed x   [tile][kb16][blk]
__device__ __align__(128) __half g_qp[(size_t)BT*HH];      // packed q   [tile][kb2][blk]
__device__ __align__(128) __half g_kp[(size_t)BT*HH];      // packed k
__device__ __align__(128) float  g_v [(size_t)BT*HH];      // fp32 rows (scaled later)
__device__ __align__(128) __half g_Wp[3*(size_t)HH*DD];    // packed W^T [sel][kb16][blk]
__device__ __align__(128) __half g_Vp[(size_t)BB*HH*TT];   // packed V'  [b][kb32][blk]
__device__ __align__(128) float  g_colsum[BT];
__device__ __align__(128) __half g_Ep[(size_t)BB*TT*TT];   // packed E   [b*16+qt][kb32][blk]

// packed offset within a block (r in 0..127, c in 0..63 halves)
__device__ __forceinline__ uint32_t pk(int r, int c) {
    return (uint32_t)(r * 64 + ((((c >> 3) ^ (r & 7))) << 3) + (c & 7));
}

// ---------------- helpers ----------------
__device__ __forceinline__ uint32_t smem_u32(const void* p) {
    uint32_t a;
    asm("{ .reg .u64 t; cvta.to.shared.u64 t, %1; cvt.u32.u64 %0, t; }" : "=r"(a) : "l"(p));
    return a;
}
__device__ __forceinline__ void ldsm4(uint32_t& r0, uint32_t& r1, uint32_t& r2, uint32_t& r3,
                                      uint32_t addr) {
    asm volatile("ldmatrix.sync.aligned.m8n8.x4.shared.b16 {%0,%1,%2,%3}, [%4];"
                 : "=r"(r0), "=r"(r1), "=r"(r2), "=r"(r3) : "r"(addr));
}
__device__ __forceinline__ void mma16(float* c, const uint32_t* a, const uint32_t* b) {
    asm volatile(
        "mma.sync.aligned.m16n8k16.row.col.f32.f16.f16.f32 "
        "{%0,%1,%2,%3}, {%4,%5,%6,%7}, {%8,%9}, {%0,%1,%2,%3};"
        : "+f"(c[0]), "+f"(c[1]), "+f"(c[2]), "+f"(c[3])
        : "r"(a[0]), "r"(a[1]), "r"(a[2]), "r"(a[3]), "r"(b[0]), "r"(b[1]));
}

#define MBARRIER_INIT(mbar, cnt) \
    asm volatile("mbarrier.init.shared.b64 [%0], %1;" :: "r"(mbar), "r"(cnt) : "memory")
#define MBARRIER_EXPECT_TX(mbar, bytes) \
    asm volatile("mbarrier.arrive.expect_tx.shared.b64 _, [%0], %1;" \
                 :: "r"(mbar), "r"(bytes) : "memory")
#define MBARRIER_WAIT_PARITY(mbar, par) do { \
    uint32_t _m = (mbar), _p = (par), _d; \
    asm volatile("{ .reg .pred p; mbarrier.try_wait.parity.acquire.cta.shared::cta.b64 p, [%1], %2; selp.b32 %0,1,0,p; }" \
                 : "=r"(_d) : "r"(_m), "r"(_p) : "memory"); \
    if (!_d) { \
        asm volatile("{ .reg .pred P1;\nWL_%=:\n mbarrier.try_wait.parity.acquire.cta.shared::cta.b64 P1, [%0], %1, 0x989680;\n @P1 bra.uni WD_%=;\n bra.uni WL_%=;\nWD_%=:\n}" \
                     :: "r"(_m), "r"(_p) : "memory"); \
    } \
} while (0)

__device__ __forceinline__ void bulk_cp(uint32_t dst, const __half* src, int bytes,
                                        uint32_t mbar) {
    asm volatile(
        "cp.async.bulk.shared::cluster.global.mbarrier::complete_tx::bytes [%0], [%1], %2, [%3];"
        :: "r"(dst), "l"(src), "r"(bytes), "r"(mbar) : "memory");
}

#define NSTAGE 3
#define STAGE_BYTES (2*BLKB)                 // 32768
#define GEMM_SMEM (64 + NSTAGE*STAGE_BYTES)  // 98368  (2 CTAs/SM)
#define SC_SMEM   (64 + 3*2*BLKB)            // q + 2 k bufs = 98368 (2 CTAs/SM)

// warp tile 64(M) x 32(N), packed smem (pitch 128 B, baked XOR). BK=64 slab.
__device__ __forceinline__ void compute_tile(uint32_t sA, uint32_t sB,
                                             int lane, int wm, int wn,
                                             float c[4][4][4]) {
    const int rbase_a = wm * 64 + (lane & 15);
    const int rbase_b = wn * 32 + (lane & 7) + ((lane >> 4) << 3);
    const uint32_t rx = (uint32_t)((lane & 7) << 4);
    const int lha = lane >> 4;
    const int lhb = (lane >> 3) & 1;
    uint32_t arow[4], brow[2];
    #pragma unroll
    for (int mt = 0; mt < 4; mt++) arow[mt] = sA + (rbase_a + mt * 16) * 128;
    #pragma unroll
    for (int np = 0; np < 2; np++) brow[np] = sB + (rbase_b + np * 16) * 128;

    #pragma unroll
    for (int ks = 0; ks < 4; ks++) {
        const uint32_t cba = ((uint32_t)((ks * 2 + lha) << 4)) ^ rx;
        const uint32_t cbb = ((uint32_t)((ks * 2 + lhb) << 4)) ^ rx;
        uint32_t a[4][4], b[4][2];
        #pragma unroll
        for (int mt = 0; mt < 4; mt++)
            ldsm4(a[mt][0], a[mt][1], a[mt][2], a[mt][3], arow[mt] + cba);
        #pragma unroll
        for (int np = 0; np < 2; np++)
            ldsm4(b[2*np][0], b[2*np][1], b[2*np+1][0], b[2*np+1][1], brow[np] + cbb);
        #pragma unroll
        for (int mt = 0; mt < 4; mt++)
            #pragma unroll
            for (int nt = 0; nt < 4; nt++)
                mma16(c[mt][nt], a[mt], b[nt]);
    }
}

__device__ __forceinline__ void compute_tile_k128(uint32_t sA, uint32_t sB,
                                                  int lane, int wm, int wn,
                                                  float c[4][4][4]) {
    compute_tile(sA,        sB,        lane, wm, wn, c);
    compute_tile(sA + BLKB, sB + BLKB, lane, wm, wn, c);
}

// block GEMM over packed blocks: A/B are arrays of 16KB blocks (stride BLKH halves)
__device__ __forceinline__ void gemm_main(const __half* __restrict__ Ablk,
                                          const __half* __restrict__ Bblk,
                                          int nkb, int tid, float c[4][4][4]) {
    extern __shared__ __half smh[];
    const uint32_t smb = smem_u32(smh);
    const int wid = tid >> 5, lane = tid & 31;
    const int wm = wid & 1, wn = wid >> 1;

    __syncthreads();
    if (tid == 0) {
        MBARRIER_INIT(smb + 0,  1);
        MBARRIER_INIT(smb + 8,  1);
        MBARRIER_INIT(smb + 16, 1);
    }
    __syncthreads();

    if (tid == 0) {
        MBARRIER_EXPECT_TX(smb + 0, 2 * BLKB);
        bulk_cp(smb + 64,            Ablk, BLKB, smb + 0);
        bulk_cp(smb + 64 + BLKB,     Bblk, BLKB, smb + 0);
        if (nkb > 1) {
            MBARRIER_EXPECT_TX(smb + 8, 2 * BLKB);
            bulk_cp(smb + 64 + STAGE_BYTES,        Ablk + BLKH, BLKB, smb + 8);
            bulk_cp(smb + 64 + STAGE_BYTES + BLKB, Bblk + BLKH, BLKB, smb + 8);
        }
    }

    int ph0 = 0, ph1 = 0, ph2 = 0;
    for (int kb = 0; kb < nkb; kb++) {
        const int st = kb % NSTAGE;
        if (st == 0)      { MBARRIER_WAIT_PARITY(smb + 0,  ph0); ph0 ^= 1; }
        else if (st == 1) { MBARRIER_WAIT_PARITY(smb + 8,  ph1); ph1 ^= 1; }
        else              { MBARRIER_WAIT_PARITY(smb + 16, ph2); ph2 ^= 1; }
        __syncthreads();
        if (kb + 2 < nkb && tid == 0) {
            const int ns = (kb + 2) % NSTAGE;
            const uint32_t mb = smb + ns * 8;
            const uint32_t base = smb + 64 + ns * STAGE_BYTES;
            MBARRIER_EXPECT_TX(mb, 2 * BLKB);
            bulk_cp(base,        Ablk + (size_t)(kb + 2) * BLKH, BLKB, mb);
            bulk_cp(base + BLKB, Bblk + (size_t)(kb + 2) * BLKH, BLKB, mb);
        }
        const uint32_t base = smb + 64 + (uint32_t)st * STAGE_BYTES;
        compute_tile(base, base + BLKB, lane, wm, wn, c);
    }
}

#define ZERO_ACC(c) do { \
    _Pragma("unroll") for (int m = 0; m < 4; m++) \
    _Pragma("unroll") for (int n = 0; n < 4; n++) \
    _Pragma("unroll") for (int i = 0; i < 4; i++) (c)[m][n][i] = 0.f; } while (0)

// shared projection body (one 128-row tile x one sel)
__device__ __forceinline__ void proj_body(int sel, int tile, int tid,
                                          const float* __restrict__ bias) {
    const int row0 = tile * 128;
    float c[4][4][4];
    ZERO_ACC(c);
    gemm_main(g_xp + (size_t)tile * (16 * BLKH),
              g_Wp + (size_t)sel * (16 * BLKH), 16, tid, c);

    const int wid = tid >> 5, lane = tid & 31;
    const int wm = wid & 1, wn = wid >> 1;
    const int tr = lane >> 2, tc = lane & 3;
    const float sc = (sel == 0) ? 0.08838834764831845f : 1.0f;

    #pragma unroll
    for (int mt = 0; mt < 4; mt++) {
        const int rloc = wm * 64 + mt * 16 + tr;
        #pragma unroll
        for (int nt = 0; nt < 4; nt++) {
            const int col = wn * 32 + nt * 8 + tc * 2;
            const float b0 = bias[col], b1 = bias[col + 1];
            float lx = (c[mt][nt][0] + b0) * sc;
            float ly = (c[mt][nt][1] + b1) * sc;
            float hx = (c[mt][nt][2] + b0) * sc;
            float hy = (c[mt][nt][3] + b1) * sc;
            if (sel != 2) {
                __half* dst = (sel == 0) ? g_qp : g_kp;
                dst += (size_t)tile * (2 * BLKH) + (size_t)(col >> 6) * BLKH;
                *(__half2*)(dst + pk(rloc,     col & 63)) = __floats2half2_rn(lx, ly);
                *(__half2*)(dst + pk(rloc + 8, col & 63)) = __floats2half2_rn(hx, hy);
            } else {
                *(float2*)(g_v + (size_t)(row0 + rloc) * HH + col)     = make_float2(lx, ly);
                *(float2*)(g_v + (size_t)(row0 + rloc + 8) * HH + col) = make_float2(hx, hy);
            }
        }
    }
}

// scores body: persistent row-pair walker (half, p, b)
__device__ __forceinline__ void scores_body(int half, int p, int b, int tid) {
    extern __shared__ __half smh[];
    const uint32_t smb = smem_u32(smh);
    const int start = half ? 8 : 0;
    const int end   = half ? 17 : 8;
    const int wid = tid >> 5, lane = tid & 31;
    const int wm = wid & 1, wn = wid >> 1;
    const int tr = lane >> 2, tc = lane & 3;

    const uint32_t qbase = smb + 64;
    const uint32_t kbase0 = qbase + 2 * BLKB;
    const uint32_t kbase1 = kbase0 + 2 * BLKB;

    __shared__ float red[128];

    if (tid == 0) {
        MBARRIER_INIT(smb + 0, 1);
        MBARRIER_INIT(smb + 8, 1);
        MBARRIER_INIT(smb + 16, 1);
    }
    __syncthreads();

    auto qt_of = [&](int u) { return (u <= p) ? p : 15 - p; };
    auto kt_of = [&](int u) { return (u <= p) ? u : u - p - 1; };

    if (tid == 0) {
        MBARRIER_EXPECT_TX(smb + 0, 2 * BLKB);
        bulk_cp(qbase, g_qp + (size_t)(b * 16 + qt_of(start)) * (2 * BLKH), 2 * BLKB, smb + 0);
        MBARRIER_EXPECT_TX(smb + 8, 2 * BLKB);
        bulk_cp(kbase0, g_kp + (size_t)(b * 16 + kt_of(start)) * (2 * BLKH), 2 * BLKB, smb + 8);
        if (start + 1 < end) {
            MBARRIER_EXPECT_TX(smb + 16, 2 * BLKB);
            bulk_cp(kbase1, g_kp + (size_t)(b * 16 + kt_of(start + 1)) * (2 * BLKH),
                    2 * BLKB, smb + 16);
        }
    }
    MBARRIER_WAIT_PARITY(smb + 0, 0);

    int cur_qt = qt_of(start);
    int kph0 = 0, kph1 = 0;

    for (int u = start; u < end; u++) {
        const int myqt = qt_of(u);
        const int mykt = kt_of(u);
        const int buf = (u - start) & 1;
        const uint32_t kb = buf ? kbase1 : kbase0;
        if (buf == 0) { MBARRIER_WAIT_PARITY(smb + 8,  kph0); kph0 ^= 1; }
        else          { MBARRIER_WAIT_PARITY(smb + 16, kph1); kph1 ^= 1; }

        if (myqt != cur_qt) {
            __syncthreads();
            if (tid == 0) {
                MBARRIER_EXPECT_TX(smb + 0, 2 * BLKB);
                bulk_cp(qbase, g_qp + (size_t)(b * 16 + myqt) * (2 * BLKH), 2 * BLKB, smb + 0);
            }
            MBARRIER_WAIT_PARITY(smb + 0, 1);
            cur_qt = myqt;
        }
        __syncthreads();

        float c[4][4][4];
        ZERO_ACC(c);
        compute_tile_k128(qbase, kb, lane, wm, wn, c);

        __syncthreads();
        if (u + 2 < end && tid == 0) {
            const uint32_t mb = buf ? (smb + 16) : (smb + 8);
            MBARRIER_EXPECT_TX(mb, 2 * BLKB);
            bulk_cp(kb, g_kp + (size_t)(b * 16 + kt_of(u + 2)) * (2 * BLKH), 2 * BLKB, mb);
        }
        if (tid < 128) red[tid] = 0.f;
        __syncthreads();

        const int q0 = myqt * 128, k0 = mykt * 128;
        const bool diag = (myqt == mykt);
        __half* eb = g_Ep + (size_t)(b * 16 + myqt) * (32 * BLKH);

        #pragma unroll
        for (int nt = 0; nt < 4; nt++) {
            const int kcol = wn * 32 + nt * 8 + tc * 2;
            const int k = k0 + kcol;
            __half* ek = eb + (size_t)(k >> 6) * BLKH;
            float cs0 = 0.f, cs1 = 0.f;
            if (!diag) {
                #pragma unroll
                for (int mt = 0; mt < 4; mt++) {
                    const int rloc = wm * 64 + mt * 16 + tr;
                    float lx = __expf(c[mt][nt][0]);
                    float ly = __expf(c[mt][nt][1]);
                    float hx = __expf(c[mt][nt][2]);
                    float hy = __expf(c[mt][nt][3]);
                    *(__half2*)(ek + pk(rloc,     k & 63)) = __floats2half2_rn(lx, ly);
                    *(__half2*)(ek + pk(rloc + 8, k & 63)) = __floats2half2_rn(hx, hy);
                    cs0 += lx + hx;
                    cs1 += ly + hy;
                }
            } else {
                #pragma unroll
                for (int mt = 0; mt < 4; mt++) {
                    const int rloc = wm * 64 + mt * 16 + tr;
                    const int q = q0 + rloc;
                    float lx = (q     >= k    ) ? __expf(c[mt][nt][0]) : 0.f;
                    float ly = (q     >= k + 1) ? __expf(c[mt][nt][1]) : 0.f;
                    float hx = (q + 8 >= k    ) ? __expf(c[mt][nt][2]) : 0.f;
                    float hy = (q + 8 >= k + 1) ? __expf(c[mt][nt][3]) : 0.f;
                    *(__half2*)(ek + pk(rloc,     k & 63)) = __floats2half2_rn(lx, ly);
                    *(__half2*)(ek + pk(rloc + 8, k & 63)) = __floats2half2_rn(hx, hy);
                    cs0 += lx + hx;
                    cs1 += ly + hy;
                }
            }
            #pragma unroll
            for (int m = 16; m >= 4; m >>= 1) {
                cs0 += __shfl_xor_sync(0xFFFFFFFF, cs0, m);
                cs1 += __shfl_xor_sync(0xFFFFFFFF, cs1, m);
            }
            if (lane < 4) {
                atomicAdd(&red[kcol],     cs0);
                atomicAdd(&red[kcol + 1], cs1);
            }
        }
        __syncthreads();
        if (tid < 128) atomicAdd(&g_colsum[(size_t)b * TT + k0 + tid], red[tid]);
    }
}

// ---------------- prep kernels ----------------
__global__ void roundx_kernel(const float* __restrict__ x, float* __restrict__ out) {
    size_t i4 = ((size_t)blockIdx.x * blockDim.x + threadIdx.x) * 4;
    float4 f = *(const float4*)(x + i4);
    __half2 h0 = __floats2half2_rn(f.x, f.y);
    __half2 h1 = __floats2half2_rn(f.z, f.w);
    const int row = (int)(i4 >> 10);
    const int col = (int)(i4 & 1023);
    __half* dst = g_xp + (size_t)(row >> 7) * (16 * BLKH) + (size_t)(col >> 6) * BLKH
                  + pk(row & 127, col & 63);
    *(__half2*)(dst)     = h0;
    *(__half2*)(dst + 2) = h1;
    if (blockIdx.x < 4096) {
        size_t j = ((size_t)blockIdx.x * blockDim.x + threadIdx.x) * 4;
        *(float4*)(out + j) = make_float4(0.f, 0.f, 0.f, 0.f);
    }
    if (blockIdx.x < 128)
        g_colsum[blockIdx.x * 256 + threadIdx.x] = 0.f;
}

__global__ void transW_kernel(const float* __restrict__ Wq, const float* __restrict__ Wk,
                              const float* __restrict__ Wv) {
    __shared__ float t[32][33];
    const int sel = blockIdx.z;
    const float* W = (sel == 0) ? Wq : (sel == 1) ? Wk : Wv;
    const int k0 = blockIdx.x * 32, n0 = blockIdx.y * 32;
    const int tx = threadIdx.x, ty = threadIdx.y;
    #pragma unroll
    for (int j = 0; j < 4; j++)
        t[ty + 8*j][tx] = W[(size_t)(k0 + ty + 8*j) * HH + n0 + tx];
    __syncthreads();
    #pragma unroll
    for (int j = 0; j < 4; j++) {
        const int n = n0 + ty + 8*j;
        const int k = k0 + tx;
        g_Wp[(size_t)(sel * 16 + (k >> 6)) * BLKH + pk(n, k & 63)] =
            __float2half_rn(t[tx][ty + 8*j]);
    }
}

__global__ void scaleV_kernel() {
    __shared__ float t[32][33];
    const int b = blockIdx.z;
    const int k0 = blockIdx.x * 32, h0 = blockIdx.y * 32;
    const int tx = threadIdx.x, ty = threadIdx.y;
    #pragma unroll
    for (int j = 0; j < 4; j++) {
        int kk = k0 + ty + 8*j;
        float inv = 1.0f / g_colsum[(size_t)b * TT + kk];
        t[ty + 8*j][tx] = g_v[((size_t)b * TT + kk) * HH + h0 + tx] * inv;
    }
    __syncthreads();
    #pragma unroll
    for (int j = 0; j < 4; j++) {
        const int h = h0 + ty + 8*j;
        const int k = k0 + tx;
        g_Vp[((size_t)b * 32 + (k >> 6)) * BLKH + pk(h, k & 63)] =
            __float2half_rn(t[tx][ty + 8*j]);
    }
}

// ---------------- proj_qk: sel in {0,1}, sel-fastest for L2 reuse ----------------
__global__ __launch_bounds__(256, 2) void proj_qk(const float* __restrict__ bq,
                                                  const float* __restrict__ bk) {
    const int sel = blockIdx.x;               // 0 or 1
    proj_body(sel, blockIdx.y, threadIdx.x, sel == 0 ? bq : bk);
}

// ---------------- fused: scores (y<8) + proj_v (y>=8) ----------------
// grid (2, 16, BB)
__global__ __launch_bounds__(256, 2) void scores_projv(const float* __restrict__ bv) {
    if (blockIdx.y < 8) {
        scores_body(blockIdx.x, blockIdx.y, blockIdx.z, threadIdx.x);
    } else {
        const int tile = (((int)blockIdx.y - 8) * 16 + (int)blockIdx.z) * 2 + (int)blockIdx.x;
        proj_body(2, tile, threadIdx.x, bv);
    }
}

// ---------------- pv: split-k, packed blocks, chunks <= 8 slabs ----------------
__global__ __launch_bounds__(256, 2) void pv_tc(float* __restrict__ out) {
    const int tid = threadIdx.x;
    const int b = blockIdx.y;
    const int wid = tid >> 5, lane = tid & 31;
    const int wm = wid & 1, wn = wid >> 1;
    const int tr = lane >> 2, tc = lane & 3;

    int id = blockIdx.x, qt = 0, ch = 0;
    #pragma unroll
    for (int q = 0; q < 16; q++) {
        int nch = (2 * (q + 1) + 7) >> 3;
        if (id < nch) { qt = q; ch = id; break; }
        id -= nch;
    }
    const int q0 = qt * 128;
    const int nkb_tot = (qt + 1) * 2;
    const int kb0 = ch * 8;
    const int nkb = min(8, nkb_tot - kb0);
    const bool whole = (kb0 == 0 && nkb == nkb_tot);

    float c[4][4][4];
    ZERO_ACC(c);
    gemm_main(g_Ep + (size_t)(b * 16 + qt) * (32 * BLKH) + (size_t)kb0 * BLKH,
              g_Vp + (size_t)b * (32 * BLKH) + (size_t)kb0 * BLKH, nkb, tid, c);

    #pragma unroll
    for (int mt = 0; mt < 4; mt++) {
        const int q = q0 + wm * 64 + mt * 16 + tr;
        #pragma unroll
        for (int nt = 0; nt < 4; nt++) {
            const int col = wn * 32 + nt * 8 + tc * 2;
            float* p0 = out + ((size_t)b * TT + q) * HH + col;
            float* p1 = out + ((size_t)b * TT + q + 8) * HH + col;
            if (whole) {
                *(float2*)p0 = make_float2(c[mt][nt][0], c[mt][nt][1]);
                *(float2*)p1 = make_float2(c[mt][nt][2], c[mt][nt][3]);
            } else {
                atomicAdd(p0,     c[mt][nt][0]);
                atomicAdd(p0 + 1, c[mt][nt][1]);
                atomicAdd(p1,     c[mt][nt][2]);
                atomicAdd(p1 + 1, c[mt][nt][3]);
            }
        }
    }
}

// ---------------- launch ----------------
extern "C" void kernel_launch(void* const* d_in, const int* in_sizes, int n_in,
                              void* d_out, int out_size) {
    const float* x  = (const float*)d_in[0];
    const float* Wk = (const float*)d_in[1];
    const float* bk = (const float*)d_in[2];
    const float* Wq = (const float*)d_in[3];
    const float* bq = (const float*)d_in[4];
    const float* Wv = (const float*)d_in[5];
    const float* bv = (const float*)d_in[6];
    float* out = (float*)d_out;

    cudaFuncSetAttribute(proj_qk,      cudaFuncAttributeMaxDynamicSharedMemorySize, GEMM_SMEM);
    cudaFuncSetAttribute(scores_projv, cudaFuncAttributeMaxDynamicSharedMemorySize, SC_SMEM);
    cudaFuncSetAttribute(pv_tc,        cudaFuncAttributeMaxDynamicSharedMemorySize, GEMM_SMEM);

    roundx_kernel<<<(size_t)BT * DD / 1024, 256>>>(x, out);
    transW_kernel<<<dim3(DD/32, HH/32, 3), dim3(32, 8)>>>(Wq, Wk, Wv);
    proj_qk<<<dim3(2, BT/128), 256, GEMM_SMEM>>>(bq, bk);
    scores_projv<<<dim3(2, 16, BB), 256, SC_SMEM>>>(bv);
    scaleV_kernel<<<dim3(TT/32, HH/32, BB), dim3(32, 8)>>>();
    pv_tc<<<dim3(40, BB), 256, GEMM_SMEM>>>(out);
}

// round 16
// speedup vs baseline: 1.0639x; 1.0639x over previous
#include <cuda_runtime.h>
#include <cuda_fp16.h>
#include <cstdint>

#define BB 16
#define TT 2048
#define DD 1024
#define HH 128
#define BT (BB*TT)

// Packed block: 128 rows x 64 halves = 8192 halves = 16384 B, SW-XOR baked in.
#define BLKH 8192
#define BLKB 16384

// ---------------- device scratch (allocation-free rule) ----------------
__device__ __align__(128) __half g_xp[(size_t)BT*DD];      // packed x   [tile][kb16][blk]
__device__ __align__(128) __half g_qp[(size_t)BT*HH];      // packed q   [tile][kb2][blk]
__device__ __align__(128) __half g_kp[(size_t)BT*HH];      // packed k
__device__ __align__(128) float  g_v [(size_t)BT*HH];      // fp32 rows (scaled later)
__device__ __align__(128) __half g_Wp[3*(size_t)HH*DD];    // packed W^T [sel][kb16][blk]
__device__ __align__(128) __half g_Vp[(size_t)BB*HH*TT];   // packed V'  [b][kb32][blk]
__device__ __align__(128) float  g_colsum[BT];
__device__ __align__(128) __half g_Ep[(size_t)BB*TT*TT];   // packed E   [b*16+qt][kb32][blk]

// packed offset within a block (r in 0..127, c in 0..63 halves)
__device__ __forceinline__ uint32_t pk(int r, int c) {
    return (uint32_t)(r * 64 + ((((c >> 3) ^ (r & 7))) << 3) + (c & 7));
}

// ---------------- helpers ----------------
__device__ __forceinline__ uint32_t smem_u32(const void* p) {
    uint32_t a;
    asm("{ .reg .u64 t; cvta.to.shared.u64 t, %1; cvt.u32.u64 %0, t; }" : "=r"(a) : "l"(p));
    return a;
}
__device__ __forceinline__ void ldsm4(uint32_t& r0, uint32_t& r1, uint32_t& r2, uint32_t& r3,
                                      uint32_t addr) {
    asm volatile("ldmatrix.sync.aligned.m8n8.x4.shared.b16 {%0,%1,%2,%3}, [%4];"
                 : "=r"(r0), "=r"(r1), "=r"(r2), "=r"(r3) : "r"(addr));
}
__device__ __forceinline__ void mma16(float* c, const uint32_t* a, const uint32_t* b) {
    asm volatile(
        "mma.sync.aligned.m16n8k16.row.col.f32.f16.f16.f32 "
        "{%0,%1,%2,%3}, {%4,%5,%6,%7}, {%8,%9}, {%0,%1,%2,%3};"
        : "+f"(c[0]), "+f"(c[1]), "+f"(c[2]), "+f"(c[3])
        : "r"(a[0]), "r"(a[1]), "r"(a[2]), "r"(a[3]), "r"(b[0]), "r"(b[1]));
}

#define MBARRIER_INIT(mbar, cnt) \
    asm volatile("mbarrier.init.shared.b64 [%0], %1;" :: "r"(mbar), "r"(cnt) : "memory")
#define MBARRIER_EXPECT_TX(mbar, bytes) \
    asm volatile("mbarrier.arrive.expect_tx.shared.b64 _, [%0], %1;" \
                 :: "r"(mbar), "r"(bytes) : "memory")
#define MBARRIER_WAIT_PARITY(mbar, par) do { \
    uint32_t _m = (mbar), _p = (par), _d; \
    asm volatile("{ .reg .pred p; mbarrier.try_wait.parity.acquire.cta.shared::cta.b64 p, [%1], %2; selp.b32 %0,1,0,p; }" \
                 : "=r"(_d) : "r"(_m), "r"(_p) : "memory"); \
    if (!_d) { \
        asm volatile("{ .reg .pred P1;\nWL_%=:\n mbarrier.try_wait.parity.acquire.cta.shared::cta.b64 P1, [%0], %1, 0x989680;\n @P1 bra.uni WD_%=;\n bra.uni WL_%=;\nWD_%=:\n}" \
                     :: "r"(_m), "r"(_p) : "memory"); \
    } \
} while (0)

__device__ __forceinline__ void bulk_cp(uint32_t dst, const __half* src, int bytes,
                                        uint32_t mbar) {
    asm volatile(
        "cp.async.bulk.shared::cluster.global.mbarrier::complete_tx::bytes [%0], [%1], %2, [%3];"
        :: "r"(dst), "l"(src), "r"(bytes), "r"(mbar) : "memory");
}

#define NSTAGE 3
#define STAGE_BYTES (2*BLKB)                 // 32768
#define GEMM_SMEM (64 + NSTAGE*STAGE_BYTES)  // 98368  (2 CTAs/SM)
#define SC_SMEM   (64 + 3*2*BLKB)            // q + 2 k bufs = 98368 (2 CTAs/SM)

// warp tile 64(M) x 32(N), packed smem (pitch 128 B, baked XOR). BK=64 slab.
__device__ __forceinline__ void compute_tile(uint32_t sA, uint32_t sB,
                                             int lane, int wm, int wn,
                                             float c[4][4][4]) {
    const int rbase_a = wm * 64 + (lane & 15);
    const int rbase_b = wn * 32 + (lane & 7) + ((lane >> 4) << 3);
    const uint32_t rx = (uint32_t)((lane & 7) << 4);
    const int lha = lane >> 4;
    const int lhb = (lane >> 3) & 1;
    uint32_t arow[4], brow[2];
    #pragma unroll
    for (int mt = 0; mt < 4; mt++) arow[mt] = sA + (rbase_a + mt * 16) * 128;
    #pragma unroll
    for (int np = 0; np < 2; np++) brow[np] = sB + (rbase_b + np * 16) * 128;

    #pragma unroll
    for (int ks = 0; ks < 4; ks++) {
        const uint32_t cba = ((uint32_t)((ks * 2 + lha) << 4)) ^ rx;
        const uint32_t cbb = ((uint32_t)((ks * 2 + lhb) << 4)) ^ rx;
        uint32_t a[4][4], b[4][2];
        #pragma unroll
        for (int mt = 0; mt < 4; mt++)
            ldsm4(a[mt][0], a[mt][1], a[mt][2], a[mt][3], arow[mt] + cba);
        #pragma unroll
        for (int np = 0; np < 2; np++)
            ldsm4(b[2*np][0], b[2*np][1], b[2*np+1][0], b[2*np+1][1], brow[np] + cbb);
        #pragma unroll
        for (int mt = 0; mt < 4; mt++)
            #pragma unroll
            for (int nt = 0; nt < 4; nt++)
                mma16(c[mt][nt], a[mt], b[nt]);
    }
}

__device__ __forceinline__ void compute_tile_k128(uint32_t sA, uint32_t sB,
                                                  int lane, int wm, int wn,
                                                  float c[4][4][4]) {
    compute_tile(sA,        sB,        lane, wm, wn, c);
    compute_tile(sA + BLKB, sB + BLKB, lane, wm, wn, c);
}

// block GEMM over packed blocks: A/B are arrays of 16KB blocks (stride BLKH halves)
__device__ __forceinline__ void gemm_main(const __half* __restrict__ Ablk,
                                          const __half* __restrict__ Bblk,
                                          int nkb, int tid, float c[4][4][4]) {
    extern __shared__ __half smh[];
    const uint32_t smb = smem_u32(smh);
    const int wid = tid >> 5, lane = tid & 31;
    const int wm = wid & 1, wn = wid >> 1;

    __syncthreads();
    if (tid == 0) {
        MBARRIER_INIT(smb + 0,  1);
        MBARRIER_INIT(smb + 8,  1);
        MBARRIER_INIT(smb + 16, 1);
    }
    __syncthreads();

    if (tid == 0) {
        MBARRIER_EXPECT_TX(smb + 0, 2 * BLKB);
        bulk_cp(smb + 64,            Ablk, BLKB, smb + 0);
        bulk_cp(smb + 64 + BLKB,     Bblk, BLKB, smb + 0);
        if (nkb > 1) {
            MBARRIER_EXPECT_TX(smb + 8, 2 * BLKB);
            bulk_cp(smb + 64 + STAGE_BYTES,        Ablk + BLKH, BLKB, smb + 8);
            bulk_cp(smb + 64 + STAGE_BYTES + BLKB, Bblk + BLKH, BLKB, smb + 8);
        }
    }

    int ph0 = 0, ph1 = 0, ph2 = 0;
    for (int kb = 0; kb < nkb; kb++) {
        const int st = kb % NSTAGE;
        if (st == 0)      { MBARRIER_WAIT_PARITY(smb + 0,  ph0); ph0 ^= 1; }
        else if (st == 1) { MBARRIER_WAIT_PARITY(smb + 8,  ph1); ph1 ^= 1; }
        else              { MBARRIER_WAIT_PARITY(smb + 16, ph2); ph2 ^= 1; }
        __syncthreads();
        if (kb + 2 < nkb && tid == 0) {
            const int ns = (kb + 2) % NSTAGE;
            const uint32_t mb = smb + ns * 8;
            const uint32_t base = smb + 64 + ns * STAGE_BYTES;
            MBARRIER_EXPECT_TX(mb, 2 * BLKB);
            bulk_cp(base,        Ablk + (size_t)(kb + 2) * BLKH, BLKB, mb);
            bulk_cp(base + BLKB, Bblk + (size_t)(kb + 2) * BLKH, BLKB, mb);
        }
        const uint32_t base = smb + 64 + (uint32_t)st * STAGE_BYTES;
        compute_tile(base, base + BLKB, lane, wm, wn, c);
    }
}

#define ZERO_ACC(c) do { \
    _Pragma("unroll") for (int m = 0; m < 4; m++) \
    _Pragma("unroll") for (int n = 0; n < 4; n++) \
    _Pragma("unroll") for (int i = 0; i < 4; i++) (c)[m][n][i] = 0.f; } while (0)

// ---------------- prep: roundx + zero + transW (fused) ----------------
// blocks [0, 32768): pack x; also zero out (first 4096) and colsum (first 128).
// blocks [32768, 32768+384): transpose+pack W (sel = t/128, 32x32 tiles).
__global__ void prep_kernel(const float* __restrict__ x, float* __restrict__ out,
                            const float* __restrict__ Wq, const float* __restrict__ Wk,
                            const float* __restrict__ Wv) {
    __shared__ float t[32][33];
    const int tid = threadIdx.x;
    if (blockIdx.x < 32768) {
        size_t i4 = ((size_t)blockIdx.x * 256 + tid) * 4;
        float4 f = *(const float4*)(x + i4);
        __half2 h0 = __floats2half2_rn(f.x, f.y);
        __half2 h1 = __floats2half2_rn(f.z, f.w);
        const int row = (int)(i4 >> 10);
        const int col = (int)(i4 & 1023);
        __half* dst = g_xp + (size_t)(row >> 7) * (16 * BLKH) + (size_t)(col >> 6) * BLKH
                      + pk(row & 127, col & 63);
        *(__half2*)(dst)     = h0;
        *(__half2*)(dst + 2) = h1;
        if (blockIdx.x < 4096) {
            size_t j = ((size_t)blockIdx.x * 256 + tid) * 4;
            *(float4*)(out + j) = make_float4(0.f, 0.f, 0.f, 0.f);
        }
        if (blockIdx.x < 128)
            g_colsum[blockIdx.x * 256 + tid] = 0.f;
    } else {
        const int bt = blockIdx.x - 32768;     // 0..383
        const int sel = bt >> 7;               // /128
        const int r = bt & 127;                // 32 k-tiles x 4 n-tiles
        const int k0 = (r >> 2) * 32;
        const int n0 = (r & 3) * 32;
        const float* W = (sel == 0) ? Wq : (sel == 1) ? Wk : Wv;
        const int tx = tid & 31, ty = tid >> 5;
        #pragma unroll
        for (int j = 0; j < 4; j++)
            t[ty + 8*j][tx] = W[(size_t)(k0 + ty + 8*j) * HH + n0 + tx];
        __syncthreads();
        #pragma unroll
        for (int j = 0; j < 4; j++) {
            const int n = n0 + ty + 8*j;
            const int k = k0 + tx;
            g_Wp[(size_t)(sel * 16 + (k >> 6)) * BLKH + pk(n, k & 63)] =
                __float2half_rn(t[tx][ty + 8*j]);
        }
    }
}

__global__ void scaleV_kernel() {
    __shared__ float t[32][33];
    const int b = blockIdx.z;
    const int k0 = blockIdx.x * 32, h0 = blockIdx.y * 32;
    const int tx = threadIdx.x, ty = threadIdx.y;
    #pragma unroll
    for (int j = 0; j < 4; j++) {
        int kk = k0 + ty + 8*j;
        float inv = 1.0f / g_colsum[(size_t)b * TT + kk];
        t[ty + 8*j][tx] = g_v[((size_t)b * TT + kk) * HH + h0 + tx] * inv;
    }
    __syncthreads();
    #pragma unroll
    for (int j = 0; j < 4; j++) {
        const int h = h0 + ty + 8*j;
        const int k = k0 + tx;
        g_Vp[((size_t)b * 32 + (k >> 6)) * BLKH + pk(h, k & 63)] =
            __float2half_rn(t[tx][ty + 8*j]);
    }
}

// ---------------- proj (sel-fastest grid for L2 reuse of x tiles) ----------------
__global__ __launch_bounds__(256, 2) void proj_tc(const float* __restrict__ bq,
                                                  const float* __restrict__ bk,
                                                  const float* __restrict__ bv) {
    const int tid = threadIdx.x;
    const int sel = blockIdx.x;
    const int tile = blockIdx.y;
    const int row0 = tile * 128;

    float c[4][4][4];
    ZERO_ACC(c);
    gemm_main(g_xp + (size_t)tile * (16 * BLKH),
              g_Wp + (size_t)sel * (16 * BLKH), 16, tid, c);

    const int wid = tid >> 5, lane = tid & 31;
    const int wm = wid & 1, wn = wid >> 1;
    const int tr = lane >> 2, tc = lane & 3;
    const float* bias = (sel == 0) ? bq : (sel == 1) ? bk : bv;
    const float sc = (sel == 0) ? 0.08838834764831845f : 1.0f;

    #pragma unroll
    for (int mt = 0; mt < 4; mt++) {
        const int rloc = wm * 64 + mt * 16 + tr;
        #pragma unroll
        for (int nt = 0; nt < 4; nt++) {
            const int col = wn * 32 + nt * 8 + tc * 2;
            const float b0 = bias[col], b1 = bias[col + 1];
            float lx = (c[mt][nt][0] + b0) * sc;
            float ly = (c[mt][nt][1] + b1) * sc;
            float hx = (c[mt][nt][2] + b0) * sc;
            float hy = (c[mt][nt][3] + b1) * sc;
            if (sel != 2) {
                __half* dst = (sel == 0) ? g_qp : g_kp;
                dst += (size_t)tile * (2 * BLKH) + (size_t)(col >> 6) * BLKH;
                *(__half2*)(dst + pk(rloc,     col & 63)) = __floats2half2_rn(lx, ly);
                *(__half2*)(dst + pk(rloc + 8, col & 63)) = __floats2half2_rn(hx, hy);
            } else {
                *(float2*)(g_v + (size_t)(row0 + rloc) * HH + col)     = make_float2(lx, ly);
                *(float2*)(g_v + (size_t)(row0 + rloc + 8) * HH + col) = make_float2(hx, hy);
            }
        }
    }
}

// ---------------- scores: persistent row-pair walker ----------------
__global__ __launch_bounds__(256, 2) void scores_tc() {
    const int half = blockIdx.x;
    const int p    = blockIdx.y;
    const int b    = blockIdx.z;
    const int start = half ? 8 : 0;
    const int end   = half ? 17 : 8;

    extern __shared__ __half smh[];
    const uint32_t smb = smem_u32(smh);
    const int tid = threadIdx.x;
    const int wid = tid >> 5, lane = tid & 31;
    const int wm = wid & 1, wn = wid >> 1;
    const int tr = lane >> 2, tc = lane & 3;

    const uint32_t qbase = smb + 64;
    const uint32_t kbase0 = qbase + 2 * BLKB;
    const uint32_t kbase1 = kbase0 + 2 * BLKB;

    __shared__ float red[128];

    if (tid == 0) {
        MBARRIER_INIT(smb + 0, 1);
        MBARRIER_INIT(smb + 8, 1);
        MBARRIER_INIT(smb + 16, 1);
    }
    __syncthreads();

    auto qt_of = [&](int u) { return (u <= p) ? p : 15 - p; };
    auto kt_of = [&](int u) { return (u <= p) ? u : u - p - 1; };

    if (tid == 0) {
        MBARRIER_EXPECT_TX(smb + 0, 2 * BLKB);
        bulk_cp(qbase, g_qp + (size_t)(b * 16 + qt_of(start)) * (2 * BLKH), 2 * BLKB, smb + 0);
        MBARRIER_EXPECT_TX(smb + 8, 2 * BLKB);
        bulk_cp(kbase0, g_kp + (size_t)(b * 16 + kt_of(start)) * (2 * BLKH), 2 * BLKB, smb + 8);
        if (start + 1 < end) {
            MBARRIER_EXPECT_TX(smb + 16, 2 * BLKB);
            bulk_cp(kbase1, g_kp + (size_t)(b * 16 + kt_of(start + 1)) * (2 * BLKH),
                    2 * BLKB, smb + 16);
        }
    }
    MBARRIER_WAIT_PARITY(smb + 0, 0);

    int cur_qt = qt_of(start);
    int kph0 = 0, kph1 = 0;

    for (int u = start; u < end; u++) {
        const int myqt = qt_of(u);
        const int mykt = kt_of(u);
        const int buf = (u - start) & 1;
        const uint32_t kb = buf ? kbase1 : kbase0;
        if (buf == 0) { MBARRIER_WAIT_PARITY(smb + 8,  kph0); kph0 ^= 1; }
        else          { MBARRIER_WAIT_PARITY(smb + 16, kph1); kph1 ^= 1; }

        if (myqt != cur_qt) {
            __syncthreads();
            if (tid == 0) {
                MBARRIER_EXPECT_TX(smb + 0, 2 * BLKB);
                bulk_cp(qbase, g_qp + (size_t)(b * 16 + myqt) * (2 * BLKH), 2 * BLKB, smb + 0);
            }
            MBARRIER_WAIT_PARITY(smb + 0, 1);
            cur_qt = myqt;
        }
        __syncthreads();

        float c[4][4][4];
        ZERO_ACC(c);
        compute_tile_k128(qbase, kb, lane, wm, wn, c);

        __syncthreads();
        if (u + 2 < end && tid == 0) {
            const uint32_t mb = buf ? (smb + 16) : (smb + 8);
            MBARRIER_EXPECT_TX(mb, 2 * BLKB);
            bulk_cp(kb, g_kp + (size_t)(b * 16 + kt_of(u + 2)) * (2 * BLKH), 2 * BLKB, mb);
        }
        if (tid < 128) red[tid] = 0.f;
        __syncthreads();

        const int q0 = myqt * 128, k0 = mykt * 128;
        const bool diag = (myqt == mykt);
        __half* eb = g_Ep + (size_t)(b * 16 + myqt) * (32 * BLKH);

        #pragma unroll
        for (int nt = 0; nt < 4; nt++) {
            const int kcol = wn * 32 + nt * 8 + tc * 2;
            const int k = k0 + kcol;
            __half* ek = eb + (size_t)(k >> 6) * BLKH;
            float cs0 = 0.f, cs1 = 0.f;
            if (!diag) {
                #pragma unroll
                for (int mt = 0; mt < 4; mt++) {
                    const int rloc = wm * 64 + mt * 16 + tr;
                    float lx = __expf(c[mt][nt][0]);
                    float ly = __expf(c[mt][nt][1]);
                    float hx = __expf(c[mt][nt][2]);
                    float hy = __expf(c[mt][nt][3]);
                    *(__half2*)(ek + pk(rloc,     k & 63)) = __floats2half2_rn(lx, ly);
                    *(__half2*)(ek + pk(rloc + 8, k & 63)) = __floats2half2_rn(hx, hy);
                    cs0 += lx + hx;
                    cs1 += ly + hy;
                }
            } else {
                #pragma unroll
                for (int mt = 0; mt < 4; mt++) {
                    const int rloc = wm * 64 + mt * 16 + tr;
                    const int q = q0 + rloc;
                    float lx = (q     >= k    ) ? __expf(c[mt][nt][0]) : 0.f;
                    float ly = (q     >= k + 1) ? __expf(c[mt][nt][1]) : 0.f;
                    float hx = (q + 8 >= k    ) ? __expf(c[mt][nt][2]) : 0.f;
                    float hy = (q + 8 >= k + 1) ? __expf(c[mt][nt][3]) : 0.f;
                    *(__half2*)(ek + pk(rloc,     k & 63)) = __floats2half2_rn(lx, ly);
                    *(__half2*)(ek + pk(rloc + 8, k & 63)) = __floats2half2_rn(hx, hy);
                    cs0 += lx + hx;
                    cs1 += ly + hy;
                }
            }
            #pragma unroll
            for (int m = 16; m >= 4; m >>= 1) {
                cs0 += __shfl_xor_sync(0xFFFFFFFF, cs0, m);
                cs1 += __shfl_xor_sync(0xFFFFFFFF, cs1, m);
            }
            if (lane < 4) {
                atomicAdd(&red[kcol],     cs0);
                atomicAdd(&red[kcol + 1], cs1);
            }
        }
        __syncthreads();
        if (tid < 128) atomicAdd(&g_colsum[(size_t)b * TT + k0 + tid], red[tid]);
    }
}

// ---------------- pv: split-k, big chunks first ----------------
__global__ __launch_bounds__(256, 2) void pv_tc(float* __restrict__ out) {
    const int tid = threadIdx.x;
    const int b = blockIdx.y;
    const int wid = tid >> 5, lane = tid & 31;
    const int wm = wid & 1, wn = wid >> 1;
    const int tr = lane >> 2, tc = lane & 3;

    int id = 39 - (int)blockIdx.x;            // big-qt chunks launch first
    int qt = 0, ch = 0;
    #pragma unroll
    for (int q = 0; q < 16; q++) {
        int nch = (2 * (q + 1) + 7) >> 3;
        if (id < nch) { qt = q; ch = id; break; }
        id -= nch;
    }
    const int q0 = qt * 128;
    const int nkb_tot = (qt + 1) * 2;
    const int kb0 = ch * 8;
    const int nkb = min(8, nkb_tot - kb0);
    const bool whole = (kb0 == 0 && nkb == nkb_tot);

    float c[4][4][4];
    ZERO_ACC(c);
    gemm_main(g_Ep + (size_t)(b * 16 + qt) * (32 * BLKH) + (size_t)kb0 * BLKH,
              g_Vp + (size_t)b * (32 * BLKH) + (size_t)kb0 * BLKH, nkb, tid, c);

    #pragma unroll
    for (int mt = 0; mt < 4; mt++) {
        const int q = q0 + wm * 64 + mt * 16 + tr;
        #pragma unroll
        for (int nt = 0; nt < 4; nt++) {
            const int col = wn * 32 + nt * 8 + tc * 2;
            float* p0 = out + ((size_t)b * TT + q) * HH + col;
            float* p1 = out + ((size_t)b * TT + q + 8) * HH + col;
            if (whole) {
                *(float2*)p0 = make_float2(c[mt][nt][0], c[mt][nt][1]);
                *(float2*)p1 = make_float2(c[mt][nt][2], c[mt][nt][3]);
            } else {
                atomicAdd(p0,     c[mt][nt][0]);
                atomicAdd(p0 + 1, c[mt][nt][1]);
                atomicAdd(p1,     c[mt][nt][2]);
                atomicAdd(p1 + 1, c[mt][nt][3]);
            }
        }
    }
}

// ---------------- launch ----------------
extern "C" void kernel_launch(void* const* d_in, const int* in_sizes, int n_in,
                              void* d_out, int out_size) {
    const float* x  = (const float*)d_in[0];
    const float* Wk = (const float*)d_in[1];
    const float* bk = (const float*)d_in[2];
    const float* Wq = (const float*)d_in[3];
    const float* bq = (const float*)d_in[4];
    const float* Wv = (const float*)d_in[5];
    const float* bv = (const float*)d_in[6];
    float* out = (float*)d_out;

    cudaFuncSetAttribute(proj_tc,   cudaFuncAttributeMaxDynamicSharedMemorySize, GEMM_SMEM);
    cudaFuncSetAttribute(scores_tc, cudaFuncAttributeMaxDynamicSharedMemorySize, SC_SMEM);
    cudaFuncSetAttribute(pv_tc,     cudaFuncAttributeMaxDynamicSharedMemorySize, GEMM_SMEM);

    prep_kernel<<<32768 + 384, 256>>>(x, out, Wq, Wk, Wv);
    proj_tc<<<dim3(3, BT/128), 256, GEMM_SMEM>>>(bq, bk, bv);
    scores_tc<<<dim3(2, 8, BB), 256, SC_SMEM>>>();
    scaleV_kernel<<<dim3(TT/32, HH/32, BB), dim3(32, 8)>>>();
    pv_tc<<<dim3(40, BB), 256, GEMM_SMEM>>>(out);
}